// round 16
// baseline (speedup 1.0000x reference)
#include <cuda_runtime.h>
#include <cuda_bf16.h>

// out[i,j] = dot(z1[i], z2[j]) if batch[i]==batch[j] && cls[i]==cls[j]
//            && !(24<=cls[i]<=26) && i!=j, else 0.
//
// Three graph nodes; all gather traffic happens BEFORE the memset so the
// post-memset node (which runs inside the memset's ~18us L2-writeback drain
// window) is load-light:
//   1. precompute: spec-scan + ILP-8 dots -> g_pair[row*32+s] = {col, val}
//   2. cudaMemsetAsync(out, 0)   (CE, ~7.2TB/s, ~84us)
//   3. replay: warp/row, lane: one coalesced 8B load + one scattered store

#define MAXM  32             // slots per row (avg ~9.5; Poisson tail-safe)
#define SPAN  8              // speculative chunks each direction (256 cols)
#define FULLM 0xffffffffu

__device__ int2 g_pair[12288 * MAXM];   // {col, val_bits}; col -1=empty, -2=overflow

__device__ __forceinline__ int lower_bound_dev(const int* __restrict__ a, int n, int v) {
    int lo = 0, hi = n;
    while (lo < hi) { int m = (lo + hi) >> 1; if (a[m] < v) lo = m + 1; else hi = m; }
    return lo;
}
__device__ __forceinline__ int upper_bound_dev(const int* __restrict__ a, int n, int v) {
    int lo = 0, hi = n;
    while (lo < hi) { int m = (lo + hi) >> 1; if (a[m] <= v) lo = m + 1; else hi = m; }
    return lo;
}
__device__ __forceinline__ float warp_reduce_add(float d) {
    d += __shfl_xor_sync(FULLM, d, 16);
    d += __shfl_xor_sync(FULLM, d, 8);
    d += __shfl_xor_sync(FULLM, d, 4);
    d += __shfl_xor_sync(FULLM, d, 2);
    d += __shfl_xor_sync(FULLM, d, 1);
    return d;
}

// Direct per-row compute+store (used for overflow rows and generic fallback).
__device__ void row_direct_d128(const float* z1, const float* z2,
                                const int* cls, const int* batch,
                                float* out, int N, int row, int ci, int lane)
{
    const int bi = batch[row];
    const int lo = lower_bound_dev(batch, N, bi);
    const int hi = upper_bound_dev(batch, N, bi);
    const float4 a = reinterpret_cast<const float4*>(z1 + (size_t)row * 128)[lane];
    float* orow = out + (size_t)row * (size_t)N;
    for (int jb = lo; jb < hi; jb += 32) {
        const int j = jb + lane;
        const bool p = (j < hi) && (j != row) && (cls[j] == ci);
        unsigned m = __ballot_sync(FULLM, p);
        while (m) {
            const int b = __ffs(m) - 1; m &= m - 1;
            const int jj = jb + b;
            const float4 v = reinterpret_cast<const float4*>(z2 + (size_t)jj * 128)[lane];
            float d = a.x * v.x + a.y * v.y + a.z * v.z + a.w * v.w;
            d = warp_reduce_add(d);
            if (lane == 0) orow[jj] = d;
        }
    }
}

// Node 1: precompute (clean L2). Warp per row.
__global__ void __launch_bounds__(256)
precompute_pairs_d128(const float* __restrict__ z1,
                      const float* __restrict__ z2,
                      const int*  __restrict__ cls,
                      const int*  __restrict__ batch,
                      int N)
{
    __shared__ int   scol[8][MAXM];
    __shared__ float sval[8][MAXM];

    const int lane = threadIdx.x & 31;
    const int w    = threadIdx.x >> 5;
    const int row  = (blockIdx.x * blockDim.x + threadIdx.x) >> 5;
    if (row >= N) return;

    const int ci = cls[row];
    int k = 0;

    if (!(ci >= 24 && ci <= 26)) {
        const int bi = batch[row];

        // speculative loads: 8 fwd + 8 bwd chunks, independent (max MLP)
        int bF[SPAN], cF[SPAN], bB[SPAN], cB[SPAN];
        #pragma unroll
        for (int c = 0; c < SPAN; c++) {
            const int jf = row + 1 + c * 32 + lane;
            const int jfc = (jf < N) ? jf : (N - 1);
            bF[c] = batch[jfc];  cF[c] = cls[jfc];
            const int jb = row - 32 * (c + 1) + lane;
            const int jbc = (jb >= 0) ? jb : 0;
            bB[c] = batch[jbc];  cB[c] = cls[jbc];
        }

        bool doneF = false;
        #pragma unroll
        for (int c = 0; c < SPAN; c++) {
            if (doneF) continue;
            const int j = row + 1 + c * 32 + lane;
            const bool sg = (j < N) && (bF[c] == bi);
            const unsigned diffm = __ballot_sync(FULLM, !sg);
            unsigned mm = __ballot_sync(FULLM, sg && (cF[c] == ci));
            if (diffm) { const int pos = __ffs(diffm) - 1; mm &= (1u << pos) - 1u; }
            if (mm & (1u << lane)) {
                const int slot = k + __popc(mm & ((1u << lane) - 1u));
                if (slot < MAXM) scol[w][slot] = j;
            }
            k += __popc(mm);
            if (diffm) doneF = true;
        }
        if (!doneF) {
            for (int jb0 = row + 1 + SPAN * 32; jb0 < N; jb0 += 32) {
                const int j = jb0 + lane;
                const int jc = (j < N) ? j : (N - 1);
                const bool sg = (j < N) && (batch[jc] == bi);
                const unsigned diffm = __ballot_sync(FULLM, !sg);
                unsigned mm = __ballot_sync(FULLM, sg && (cls[jc] == ci));
                if (diffm) { const int pos = __ffs(diffm) - 1; mm &= (1u << pos) - 1u; }
                if (mm & (1u << lane)) {
                    const int slot = k + __popc(mm & ((1u << lane) - 1u));
                    if (slot < MAXM) scol[w][slot] = j;
                }
                k += __popc(mm);
                if (diffm) break;
            }
        }

        bool doneB = false;
        #pragma unroll
        for (int c = 0; c < SPAN; c++) {
            if (doneB) continue;
            const int j = row - 32 * (c + 1) + lane;
            const bool sg = (j >= 0) && (bB[c] == bi);
            const unsigned diffm = __ballot_sync(FULLM, !sg);
            unsigned mm = __ballot_sync(FULLM, sg && (cB[c] == ci));
            if (diffm) {
                const int pos = 31 - __clz(diffm);
                mm = (pos == 31) ? 0u : (mm & ~((1u << (pos + 1)) - 1u));
            }
            if (mm & (1u << lane)) {
                const int slot = k + __popc(mm & ((1u << lane) - 1u));
                if (slot < MAXM) scol[w][slot] = j;
            }
            k += __popc(mm);
            if (diffm) doneB = true;
        }
        if (!doneB) {
            for (int jb0 = row - 32 * (SPAN + 1); ; jb0 -= 32) {
                const int j = jb0 + lane;
                const int jc = (j >= 0) ? j : 0;
                const bool sg = (j >= 0) && (batch[jc] == bi);
                const unsigned diffm = __ballot_sync(FULLM, !sg);
                unsigned mm = __ballot_sync(FULLM, sg && (cls[jc] == ci));
                if (diffm) {
                    const int pos = 31 - __clz(diffm);
                    mm = (pos == 31) ? 0u : (mm & ~((1u << (pos + 1)) - 1u));
                }
                if (mm & (1u << lane)) {
                    const int slot = k + __popc(mm & ((1u << lane) - 1u));
                    if (slot < MAXM) scol[w][slot] = j;
                }
                k += __popc(mm);
                if (diffm) break;
            }
        }
    }
    __syncwarp();
    const int kk = min(k, MAXM);

    // dots over collected columns, ILP-8
    if (kk > 0) {
        const float4 a = reinterpret_cast<const float4*>(z1 + (size_t)row * 128)[lane];
        for (int s = 0; s < kk; s += 8) {
            int jj[8];
            #pragma unroll
            for (int q = 0; q < 8; q++)
                jj[q] = (s + q < kk) ? scol[w][s + q] : scol[w][s];
            float4 b[8];
            #pragma unroll
            for (int q = 0; q < 8; q++)
                b[q] = reinterpret_cast<const float4*>(z2 + (size_t)jj[q] * 128)[lane];
            float d[8];
            #pragma unroll
            for (int q = 0; q < 8; q++)
                d[q] = a.x * b[q].x + a.y * b[q].y + a.z * b[q].z + a.w * b[q].w;
            #pragma unroll
            for (int q = 0; q < 8; q++)
                d[q] = warp_reduce_add(d[q]);
            if (lane == 0) {
                #pragma unroll
                for (int q = 0; q < 8; q++)
                    if (s + q < kk) sval[w][s + q] = d[q];
            }
        }
    }
    __syncwarp();

    // write scratch: one int2 per lane (coalesced 256B per row)
    int2 rec;
    if (k > MAXM) {
        rec.x = (lane == 0) ? -2 : -1;      // overflow sentinel in slot 0
        rec.y = 0;
    } else if (lane < kk) {
        rec.x = scol[w][lane];
        rec.y = __float_as_int(sval[w][lane]);
    } else {
        rec.x = -1; rec.y = 0;
    }
    g_pair[row * MAXM + lane] = rec;
}

// Node 3: replay. Warp per row; lane: 1 coalesced load + 1 predicated store.
__global__ void __launch_bounds__(256)
replay_pairs_d128(const float* __restrict__ z1,
                  const float* __restrict__ z2,
                  const int*  __restrict__ cls,
                  const int*  __restrict__ batch,
                  float* __restrict__ out,
                  int N)
{
    const int lane = threadIdx.x & 31;
    const int row  = (blockIdx.x * blockDim.x + threadIdx.x) >> 5;
    if (row >= N) return;

    const int2 rec = g_pair[row * MAXM + lane];
    const unsigned ovf = __ballot_sync(FULLM, lane == 0 && rec.x == -2);
    if (ovf) {                               // never expected
        row_direct_d128(z1, z2, cls, batch, out, N, row, cls[row], lane);
        return;
    }
    if (rec.x >= 0)
        out[(size_t)row * (size_t)N + (size_t)rec.x] = __int_as_float(rec.y);
}

// ----------------- generic fallback (any D): memset + direct scatter -------
__global__ void seg_decoder_sparse_generic(const float* __restrict__ z1,
                                           const float* __restrict__ z2,
                                           const int*  __restrict__ cls,
                                           const int*  __restrict__ batch,
                                           float* __restrict__ out,
                                           int N, int D)
{
    const int lane = threadIdx.x & 31;
    const int row  = (blockIdx.x * blockDim.x + threadIdx.x) >> 5;
    if (row >= N) return;

    const int ci = cls[row];
    if (ci >= 24 && ci <= 26) return;
    const int bi = batch[row];
    const int lo = lower_bound_dev(batch, N, bi);
    const int hi = upper_bound_dev(batch, N, bi);
    const float* arow = z1 + (size_t)row * D;
    float* orow = out + (size_t)row * (size_t)N;

    for (int jb = lo; jb < hi; jb += 32) {
        const int j = jb + lane;
        const bool p = (j < hi) && (j != row) && (cls[j] == ci);
        unsigned m = __ballot_sync(FULLM, p);
        while (m) {
            const int b = __ffs(m) - 1; m &= m - 1;
            const int jj = jb + b;
            const float* vrow = z2 + (size_t)jj * D;
            float d = 0.f;
            for (int kk = lane; kk < D; kk += 32) d += arow[kk] * vrow[kk];
            d = warp_reduce_add(d);
            if (lane == 0) orow[jj] = d;
        }
    }
}

extern "C" void kernel_launch(void* const* d_in, const int* in_sizes, int n_in,
                              void* d_out, int out_size)
{
    const float* z1    = (const float*)d_in[0];
    const float* z2    = (const float*)d_in[1];
    const int*   cls   = (const int*)d_in[2];
    const int*   batch = (const int*)d_in[3];
    float*       out   = (float*)d_out;

    const int N = in_sizes[2];
    const int D = in_sizes[0] / N;
    const int blocks = (N * 32 + 255) / 256;   // one warp per row

    if (D == 128 && N <= 12288) {
        precompute_pairs_d128<<<blocks, 256>>>(z1, z2, cls, batch, N);
        cudaMemsetAsync(out, 0, (size_t)out_size * sizeof(float));
        replay_pairs_d128<<<blocks, 256>>>(z1, z2, cls, batch, out, N);
    } else {
        cudaMemsetAsync(out, 0, (size_t)out_size * sizeof(float));
        seg_decoder_sparse_generic<<<blocks, 256>>>(z1, z2, cls, batch, out, N, D);
    }
}

// round 17
// speedup vs baseline: 1.0021x; 1.0021x over previous
#include <cuda_runtime.h>
#include <cuda_bf16.h>

// out[i,j] = dot(z1[i], z2[j]) if batch[i]==batch[j] && cls[i]==cls[j]
//            && !(24<=cls[i]<=26) && i!=j, else 0.
//
// 3 nodes. Post-memset reads are the cost driver (they queue behind the
// memset's ~17us L2-writeback drain), so the tail reads only a ~1MB compact
// pair list:
//   1. precompute: lean spec-scan (SPAN=4) + ILP-8 dots -> atomic-append
//      packed (row<<14|col, val) pairs
//   2. cudaMemsetAsync(out, 0)            (CE, ~7.2TB/s, ~84us)
//   3. replay: thread-per-pair scatter; counters self-clean via last-block
//      ticket (no extra reset node; deterministic across graph replays)

#define CAP      64            // matches per row (avg ~9.5)
#define SPAN     4             // speculative chunks each direction (128 cols)
#define PAIR_CAP (1 << 18)     // 262144 pairs (actual ~117k)
#define FULLM    0xffffffffu

__device__ int      g_npairs;            // zero-initialized; self-cleaned
__device__ int      g_overflow;
__device__ int      g_done;
__device__ unsigned g_key[PAIR_CAP];     // (row << 14) | col
__device__ float    g_val[PAIR_CAP];

__device__ __forceinline__ int lower_bound_dev(const int* __restrict__ a, int n, int v) {
    int lo = 0, hi = n;
    while (lo < hi) { int m = (lo + hi) >> 1; if (a[m] < v) lo = m + 1; else hi = m; }
    return lo;
}
__device__ __forceinline__ int upper_bound_dev(const int* __restrict__ a, int n, int v) {
    int lo = 0, hi = n;
    while (lo < hi) { int m = (lo + hi) >> 1; if (a[m] <= v) lo = m + 1; else hi = m; }
    return lo;
}
__device__ __forceinline__ float warp_reduce_add(float d) {
    d += __shfl_xor_sync(FULLM, d, 16);
    d += __shfl_xor_sync(FULLM, d, 8);
    d += __shfl_xor_sync(FULLM, d, 4);
    d += __shfl_xor_sync(FULLM, d, 2);
    d += __shfl_xor_sync(FULLM, d, 1);
    return d;
}

__device__ void row_direct_d128(const float* z1, const float* z2,
                                const int* cls, const int* batch,
                                float* out, int N, int row, int lane)
{
    const int ci = cls[row];
    if (ci >= 24 && ci <= 26) return;
    const int bi = batch[row];
    const int lo = lower_bound_dev(batch, N, bi);
    const int hi = upper_bound_dev(batch, N, bi);
    const float4 a = reinterpret_cast<const float4*>(z1 + (size_t)row * 128)[lane];
    float* orow = out + (size_t)row * (size_t)N;
    for (int jb = lo; jb < hi; jb += 32) {
        const int j = jb + lane;
        const bool p = (j < hi) && (j != row) && (cls[j] == ci);
        unsigned m = __ballot_sync(FULLM, p);
        while (m) {
            const int b = __ffs(m) - 1; m &= m - 1;
            const int jj = jb + b;
            const float4 v = reinterpret_cast<const float4*>(z2 + (size_t)jj * 128)[lane];
            float d = a.x * v.x + a.y * v.y + a.z * v.z + a.w * v.w;
            d = warp_reduce_add(d);
            if (lane == 0) orow[jj] = d;
        }
    }
}

// Node 1: precompute (clean L2). Warp per row -> compact pair list.
__global__ void __launch_bounds__(256)
precompute_compact_d128(const float* __restrict__ z1,
                        const float* __restrict__ z2,
                        const int*  __restrict__ cls,
                        const int*  __restrict__ batch,
                        int N)
{
    __shared__ int   scol[8][CAP];
    __shared__ float sval[8][CAP];

    const int lane = threadIdx.x & 31;
    const int w    = threadIdx.x >> 5;
    const int row  = (blockIdx.x * blockDim.x + threadIdx.x) >> 5;
    if (row >= N) return;

    const int ci = cls[row];
    int k = 0;

    if (!(ci >= 24 && ci <= 26)) {
        const int bi = batch[row];

        // speculative loads: SPAN fwd + SPAN bwd chunks, all independent
        int bF[SPAN], cF[SPAN], bB[SPAN], cB[SPAN];
        #pragma unroll
        for (int c = 0; c < SPAN; c++) {
            const int jf = row + 1 + c * 32 + lane;
            const int jfc = (jf < N) ? jf : (N - 1);
            bF[c] = batch[jfc];  cF[c] = cls[jfc];
            const int jb = row - 32 * (c + 1) + lane;
            const int jbc = (jb >= 0) ? jb : 0;
            bB[c] = batch[jbc];  cB[c] = cls[jbc];
        }

        bool doneF = false;
        #pragma unroll
        for (int c = 0; c < SPAN; c++) {
            if (doneF) continue;
            const int j = row + 1 + c * 32 + lane;
            const bool sg = (j < N) && (bF[c] == bi);
            const unsigned diffm = __ballot_sync(FULLM, !sg);
            unsigned mm = __ballot_sync(FULLM, sg && (cF[c] == ci));
            if (diffm) { const int pos = __ffs(diffm) - 1; mm &= (1u << pos) - 1u; }
            if (mm & (1u << lane)) {
                const int slot = k + __popc(mm & ((1u << lane) - 1u));
                if (slot < CAP) scol[w][slot] = j;
            }
            k += __popc(mm);
            if (diffm) doneF = true;
        }
        if (!doneF) {
            for (int jb0 = row + 1 + SPAN * 32; jb0 < N; jb0 += 32) {
                const int j = jb0 + lane;
                const int jc = (j < N) ? j : (N - 1);
                const bool sg = (j < N) && (batch[jc] == bi);
                const unsigned diffm = __ballot_sync(FULLM, !sg);
                unsigned mm = __ballot_sync(FULLM, sg && (cls[jc] == ci));
                if (diffm) { const int pos = __ffs(diffm) - 1; mm &= (1u << pos) - 1u; }
                if (mm & (1u << lane)) {
                    const int slot = k + __popc(mm & ((1u << lane) - 1u));
                    if (slot < CAP) scol[w][slot] = j;
                }
                k += __popc(mm);
                if (diffm) break;
            }
        }

        bool doneB = false;
        #pragma unroll
        for (int c = 0; c < SPAN; c++) {
            if (doneB) continue;
            const int j = row - 32 * (c + 1) + lane;
            const bool sg = (j >= 0) && (bB[c] == bi);
            const unsigned diffm = __ballot_sync(FULLM, !sg);
            unsigned mm = __ballot_sync(FULLM, sg && (cB[c] == ci));
            if (diffm) {
                const int pos = 31 - __clz(diffm);
                mm = (pos == 31) ? 0u : (mm & ~((1u << (pos + 1)) - 1u));
            }
            if (mm & (1u << lane)) {
                const int slot = k + __popc(mm & ((1u << lane) - 1u));
                if (slot < CAP) scol[w][slot] = j;
            }
            k += __popc(mm);
            if (diffm) doneB = true;
        }
        if (!doneB) {
            for (int jb0 = row - 32 * (SPAN + 1); ; jb0 -= 32) {
                const int j = jb0 + lane;
                const int jc = (j >= 0) ? j : 0;
                const bool sg = (j >= 0) && (batch[jc] == bi);
                const unsigned diffm = __ballot_sync(FULLM, !sg);
                unsigned mm = __ballot_sync(FULLM, sg && (cls[jc] == ci));
                if (diffm) {
                    const int pos = 31 - __clz(diffm);
                    mm = (pos == 31) ? 0u : (mm & ~((1u << (pos + 1)) - 1u));
                }
                if (mm & (1u << lane)) {
                    const int slot = k + __popc(mm & ((1u << lane) - 1u));
                    if (slot < CAP) scol[w][slot] = j;
                }
                k += __popc(mm);
                if (diffm) break;
            }
        }
    }
    __syncwarp();
    const int kk = min(k, CAP);

    // dots over collected columns, ILP-8
    if (kk > 0) {
        const float4 a = reinterpret_cast<const float4*>(z1 + (size_t)row * 128)[lane];
        for (int s = 0; s < kk; s += 8) {
            int jj[8];
            #pragma unroll
            for (int q = 0; q < 8; q++)
                jj[q] = (s + q < kk) ? scol[w][s + q] : scol[w][s];
            float4 b[8];
            #pragma unroll
            for (int q = 0; q < 8; q++)
                b[q] = reinterpret_cast<const float4*>(z2 + (size_t)jj[q] * 128)[lane];
            float d[8];
            #pragma unroll
            for (int q = 0; q < 8; q++)
                d[q] = a.x * b[q].x + a.y * b[q].y + a.z * b[q].z + a.w * b[q].w;
            #pragma unroll
            for (int q = 0; q < 8; q++)
                d[q] = warp_reduce_add(d[q]);
            if (lane == 0) {
                #pragma unroll
                for (int q = 0; q < 8; q++)
                    if (s + q < kk) sval[w][s + q] = d[q];
            }
        }
    }
    __syncwarp();

    // atomic-compact append (warp-aggregated)
    int base = 0;
    if (lane == 0 && kk > 0) base = atomicAdd(&g_npairs, kk);
    base = __shfl_sync(FULLM, base, 0);
    for (int s = lane; s < kk; s += 32) {
        const int slot = base + s;
        if (slot < PAIR_CAP) {
            g_key[slot] = ((unsigned)row << 14) | (unsigned)scol[w][s];
            g_val[slot] = sval[w][s];
        }
    }
    if (lane == 0 && (k > CAP || base + kk > PAIR_CAP))
        atomicExch(&g_overflow, 1);     // never expected
}

// Node 3: replay. Thread per pair; self-cleaning counters.
__global__ void __launch_bounds__(256)
replay_compact_d128(const float* __restrict__ z1,
                    const float* __restrict__ z2,
                    const int*  __restrict__ cls,
                    const int*  __restrict__ batch,
                    float* __restrict__ out,
                    int N)
{
    const int t = blockIdx.x * blockDim.x + threadIdx.x;
    const int n   = g_npairs;
    const int ovf = g_overflow;

    if (!ovf) {
        if (t < n && t < PAIR_CAP) {
            const unsigned key = g_key[t];
            out[(size_t)(key >> 14) * (size_t)N + (size_t)(key & 0x3fffu)] = g_val[t];
        }
    } else {
        // full fallback: warp per row, direct compute (correctness path)
        const int row = t >> 5;
        if (row < N) row_direct_d128(z1, z2, cls, batch, out, N, row, t & 31);
    }

    // self-clean: last block to finish resets the counters (all blocks have
    // already read n/ovf before arriving here)
    __syncthreads();
    if (threadIdx.x == 0) {
        const int d = atomicAdd(&g_done, 1) + 1;
        if (d == (int)gridDim.x) {
            g_npairs = 0;
            g_overflow = 0;
            g_done = 0;
        }
    }
}

// ----------------- generic fallback (any D): memset + direct scatter -------
__global__ void seg_decoder_sparse_generic(const float* __restrict__ z1,
                                           const float* __restrict__ z2,
                                           const int*  __restrict__ cls,
                                           const int*  __restrict__ batch,
                                           float* __restrict__ out,
                                           int N, int D)
{
    const int lane = threadIdx.x & 31;
    const int row  = (blockIdx.x * blockDim.x + threadIdx.x) >> 5;
    if (row >= N) return;

    const int ci = cls[row];
    if (ci >= 24 && ci <= 26) return;
    const int bi = batch[row];
    const int lo = lower_bound_dev(batch, N, bi);
    const int hi = upper_bound_dev(batch, N, bi);
    const float* arow = z1 + (size_t)row * D;
    float* orow = out + (size_t)row * (size_t)N;

    for (int jb = lo; jb < hi; jb += 32) {
        const int j = jb + lane;
        const bool p = (j < hi) && (j != row) && (cls[j] == ci);
        unsigned m = __ballot_sync(FULLM, p);
        while (m) {
            const int b = __ffs(m) - 1; m &= m - 1;
            const int jj = jb + b;
            const float* vrow = z2 + (size_t)jj * D;
            float d = 0.f;
            for (int kk = lane; kk < D; kk += 32) d += arow[kk] * vrow[kk];
            d = warp_reduce_add(d);
            if (lane == 0) orow[jj] = d;
        }
    }
}

extern "C" void kernel_launch(void* const* d_in, const int* in_sizes, int n_in,
                              void* d_out, int out_size)
{
    const float* z1    = (const float*)d_in[0];
    const float* z2    = (const float*)d_in[1];
    const int*   cls   = (const int*)d_in[2];
    const int*   batch = (const int*)d_in[3];
    float*       out   = (float*)d_out;

    const int N = in_sizes[2];
    const int D = in_sizes[0] / N;
    const int blocks = (N * 32 + 255) / 256;   // 1536 for N=12288

    if (D == 128 && N <= 12288) {
        precompute_compact_d128<<<blocks, 256>>>(z1, z2, cls, batch, N);
        cudaMemsetAsync(out, 0, (size_t)out_size * sizeof(float));
        replay_compact_d128<<<blocks, 256>>>(z1, z2, cls, batch, out, N);
    } else {
        cudaMemsetAsync(out, 0, (size_t)out_size * sizeof(float));
        seg_decoder_sparse_generic<<<blocks, 256>>>(z1, z2, cls, batch, out, N, D);
    }
}